// round 1
// baseline (speedup 1.0000x reference)
#include <cuda_runtime.h>

#define BATCH 8
#define NOBS 1024
#define MOUT 1024
#define CCH 16
#define OCH 32
#define NSPLIT 16
#define NCHUNK (NOBS / NSPLIT)      // 64
#define THREADS 128
#define M_T 4
#define M_PER_BLOCK (THREADS * M_T) // 512
#define MTILES (MOUT / M_PER_BLOCK) // 2

// scratch: partial[s][b][m][c] = 16*8*1024*16 floats = 8 MB
__device__ float g_partial[(size_t)NSPLIT * BATCH * MOUT * CCH];

__device__ __forceinline__ float ex2f(float v) {
    float r;
    asm("ex2.approx.ftz.f32 %0, %1;" : "=f"(r) : "f"(v));
    return r;
}

__global__ __launch_bounds__(THREADS) void setconv_partial_kernel(
    const float* __restrict__ x, const float* __restrict__ y,
    const float* __restrict__ t, const float* __restrict__ sigma)
{
    __shared__ float  sx[NCHUNK];
    __shared__ float4 sy[NCHUNK][CCH / 4];
    __shared__ float  sq[CCH];

    const int tid = threadIdx.x;
    const int s   = blockIdx.x % NSPLIT;
    const int mt  = (blockIdx.x / NSPLIT) % MTILES;
    const int b   = blockIdx.x / (NSPLIT * MTILES);

    // q_c = (-0.5 / exp(2*sigma_c)) * log2(e)   so that w = exp2(q_c * d)
    if (tid < CCH) {
        float sg = sigma[tid];
        float inv_s2 = ex2f(-2.0f * sg * 1.4426950408889634f); // exp(-2*sigma)
        sq[tid] = -0.72134752044448170f * inv_s2;              // -0.5*log2e/s^2
    }

    const int n0 = s * NCHUNK;
    if (tid < NCHUNK) sx[tid] = x[b * NOBS + n0 + tid];

    const float4* y4 = (const float4*)(y + ((size_t)b * NOBS + n0) * CCH);
    #pragma unroll
    for (int i = tid; i < NCHUNK * CCH / 4; i += THREADS)
        ((float4*)sy)[i] = y4[i];

    __syncthreads();

    // uniform-sigma fast path detection (true for this problem's inputs)
    float q0 = sq[0];
    bool uniform = true;
    #pragma unroll
    for (int c = 1; c < CCH; c++) uniform &= (sq[c] == q0);

    float tm[M_T];
    #pragma unroll
    for (int k = 0; k < M_T; k++)
        tm[k] = t[b * MOUT + mt * M_PER_BLOCK + k * THREADS + tid];

    float acc[M_T][CCH];
    #pragma unroll
    for (int k = 0; k < M_T; k++)
        #pragma unroll
        for (int c = 0; c < CCH; c++) acc[k][c] = 0.0f;

    if (uniform) {
        #pragma unroll 4
        for (int j = 0; j < NCHUNK; j++) {
            float xn = sx[j];
            float w[M_T];
            #pragma unroll
            for (int k = 0; k < M_T; k++) {
                float d = xn - tm[k];
                w[k] = ex2f(q0 * d * d);
            }
            #pragma unroll
            for (int c4 = 0; c4 < CCH / 4; c4++) {
                float4 yv = sy[j][c4];
                #pragma unroll
                for (int k = 0; k < M_T; k++) {
                    acc[k][c4 * 4 + 0] += w[k] * yv.x;
                    acc[k][c4 * 4 + 1] += w[k] * yv.y;
                    acc[k][c4 * 4 + 2] += w[k] * yv.z;
                    acc[k][c4 * 4 + 3] += w[k] * yv.w;
                }
            }
        }
    } else {
        float qr[CCH];
        #pragma unroll
        for (int c = 0; c < CCH; c++) qr[c] = sq[c];
        for (int j = 0; j < NCHUNK; j++) {
            float xn = sx[j];
            float d[M_T];
            #pragma unroll
            for (int k = 0; k < M_T; k++) {
                float dd = xn - tm[k];
                d[k] = dd * dd;
            }
            #pragma unroll
            for (int c4 = 0; c4 < CCH / 4; c4++) {
                float4 yv = sy[j][c4];
                #pragma unroll
                for (int k = 0; k < M_T; k++) {
                    acc[k][c4 * 4 + 0] += ex2f(qr[c4 * 4 + 0] * d[k]) * yv.x;
                    acc[k][c4 * 4 + 1] += ex2f(qr[c4 * 4 + 1] * d[k]) * yv.y;
                    acc[k][c4 * 4 + 2] += ex2f(qr[c4 * 4 + 2] * d[k]) * yv.z;
                    acc[k][c4 * 4 + 3] += ex2f(qr[c4 * 4 + 3] * d[k]) * yv.w;
                }
            }
        }
    }

    // write partials
    #pragma unroll
    for (int k = 0; k < M_T; k++) {
        int m = mt * M_PER_BLOCK + k * THREADS + tid;
        float4* p = (float4*)&g_partial[(((size_t)s * BATCH + b) * MOUT + m) * CCH];
        #pragma unroll
        for (int c4 = 0; c4 < CCH / 4; c4++)
            p[c4] = make_float4(acc[k][c4 * 4 + 0], acc[k][c4 * 4 + 1],
                                acc[k][c4 * 4 + 2], acc[k][c4 * 4 + 3]);
    }
}

__global__ __launch_bounds__(128) void setconv_reduce_kernel(
    const float* __restrict__ W, const float* __restrict__ bias,
    float* __restrict__ out)
{
    __shared__ float sW[OCH * CCH];
    __shared__ float sb[OCH];
    const int tid = threadIdx.x;
    for (int i = tid; i < OCH * CCH; i += 128) sW[i] = W[i];
    if (tid < OCH) sb[tid] = bias[tid];
    __syncthreads();

    const int g = blockIdx.x * 128 + tid;  // flat (b, m)
    const int b = g / MOUT;
    const int m = g % MOUT;

    float sum[CCH];
    #pragma unroll
    for (int c = 0; c < CCH; c++) sum[c] = 0.0f;

    #pragma unroll
    for (int s = 0; s < NSPLIT; s++) {
        const float4* p = (const float4*)&g_partial[(((size_t)s * BATCH + b) * MOUT + m) * CCH];
        #pragma unroll
        for (int c4 = 0; c4 < CCH / 4; c4++) {
            float4 v = p[c4];
            sum[c4 * 4 + 0] += v.x;
            sum[c4 * 4 + 1] += v.y;
            sum[c4 * 4 + 2] += v.z;
            sum[c4 * 4 + 3] += v.w;
        }
    }

    float4* op = (float4*)(out + (size_t)g * OCH);
    #pragma unroll
    for (int o4 = 0; o4 < OCH / 4; o4++) {
        float4 r;
        float rv[4];
        #pragma unroll
        for (int u = 0; u < 4; u++) {
            int o = o4 * 4 + u;
            float acc = sb[o];
            #pragma unroll
            for (int c = 0; c < CCH; c++) acc += sum[c] * sW[o * CCH + c];
            rv[u] = acc;
        }
        r.x = rv[0]; r.y = rv[1]; r.z = rv[2]; r.w = rv[3];
        op[o4] = r;
    }
}

extern "C" void kernel_launch(void* const* d_in, const int* in_sizes, int n_in,
                              void* d_out, int out_size)
{
    const float* x     = (const float*)d_in[0];
    const float* y     = (const float*)d_in[1];
    const float* t     = (const float*)d_in[2];
    const float* sigma = (const float*)d_in[3];
    const float* W     = (const float*)d_in[4];
    const float* bias  = (const float*)d_in[5];
    float* out = (float*)d_out;

    setconv_partial_kernel<<<BATCH * MTILES * NSPLIT, THREADS>>>(x, y, t, sigma);
    setconv_reduce_kernel<<<(BATCH * MOUT) / 128, 128>>>(W, bias, out);
}

// round 2
// speedup vs baseline: 1.1440x; 1.1440x over previous
#include <cuda_runtime.h>

#define BATCH 8
#define NOBS 1024
#define MOUT 1024
#define CCH 16
#define OCH 32
#define THREADS 128
#define M_B 32            // m-values per block
#define MTILES (MOUT / M_B)      // 32
#define CHUNK 128         // n staged per smem chunk
#define NCHUNKS (NOBS / CHUNK)   // 8
#define NSUB 8            // n-parallel threads per m pair
#define NITER (CHUNK / NSUB)     // 16

__device__ __forceinline__ float ex2f(float v) {
    float r;
    asm("ex2.approx.ftz.f32 %0, %1;" : "=f"(r) : "f"(v));
    return r;
}

__global__ __launch_bounds__(THREADS) void setconv_fused_kernel(
    const float* __restrict__ x, const float* __restrict__ y,
    const float* __restrict__ t, const float* __restrict__ sigma,
    const float* __restrict__ W, const float* __restrict__ bias,
    float* __restrict__ out)
{
    __shared__ float  sx[CHUNK];                 // 0.5 KB
    __shared__ float4 sy[CHUNK][CCH / 4];        // 8 KB
    __shared__ float  sred[CCH][NSUB][M_B];      // 16 KB
    __shared__ float  yout[M_B][CCH + 1];        // padded, conflict-free
    __shared__ float  sWt[CCH][OCH];             // W transposed: [c][o]
    __shared__ float  sb[OCH];

    const int tid   = threadIdx.x;
    const int b     = blockIdx.x / MTILES;
    const int mt    = blockIdx.x % MTILES;
    const int nsub  = tid >> 4;     // 0..7  (warp has 2 distinct nsub -> smem broadcast)
    const int mslot = tid & 15;     // 0..15

    // stage W transposed + bias
    for (int i = tid; i < OCH * CCH; i += THREADS) {
        int o = i / CCH, c = i % CCH;
        sWt[c][o] = W[i];
    }
    if (tid < OCH) sb[tid] = bias[tid];

    // uniform-sigma check (true for this problem: sigma = full(log 0.1))
    float sg0 = sigma[0];
    bool uniform = true;
    #pragma unroll
    for (int c = 1; c < CCH; c++) uniform &= (sigma[c] == sg0);

    const int mbase = mt * M_B;
    const float tm0 = t[b * MOUT + mbase + mslot];
    const float tm1 = t[b * MOUT + mbase + 16 + mslot];

    float acc[2][CCH];
    #pragma unroll
    for (int k = 0; k < 2; k++)
        #pragma unroll
        for (int c = 0; c < CCH; c++) acc[k][c] = 0.0f;

    for (int ch = 0; ch < NCHUNKS; ch++) {
        __syncthreads();
        const int n0 = ch * CHUNK;
        if (tid < CHUNK) sx[tid] = x[b * NOBS + n0 + tid];
        const float4* y4 = (const float4*)(y + ((size_t)b * NOBS + n0) * CCH);
        #pragma unroll
        for (int i = tid; i < CHUNK * CCH / 4; i += THREADS)
            ((float4*)sy)[i] = y4[i];
        __syncthreads();

        if (uniform) {
            // q0 = -0.5*log2(e)/s^2 with s = exp(sigma0)
            const float q0 = -0.72134752044448170f *
                             ex2f(-2.0f * sg0 * 1.4426950408889634f);
            #pragma unroll 2
            for (int i = 0; i < NITER; i++) {
                const int nl = i * NSUB + nsub;
                const float xn = sx[nl];
                const float d0 = xn - tm0, d1 = xn - tm1;
                const float w0 = ex2f(q0 * d0 * d0);
                const float w1 = ex2f(q0 * d1 * d1);
                #pragma unroll
                for (int c4 = 0; c4 < CCH / 4; c4++) {
                    const float4 yv = sy[nl][c4];
                    acc[0][c4*4+0] += w0 * yv.x;  acc[1][c4*4+0] += w1 * yv.x;
                    acc[0][c4*4+1] += w0 * yv.y;  acc[1][c4*4+1] += w1 * yv.y;
                    acc[0][c4*4+2] += w0 * yv.z;  acc[1][c4*4+2] += w1 * yv.z;
                    acc[0][c4*4+3] += w0 * yv.w;  acc[1][c4*4+3] += w1 * yv.w;
                }
            }
        } else {
            float q[CCH];
            #pragma unroll
            for (int c = 0; c < CCH; c++)
                q[c] = -0.72134752044448170f *
                       ex2f(-2.0f * sigma[c] * 1.4426950408889634f);
            for (int i = 0; i < NITER; i++) {
                const int nl = i * NSUB + nsub;
                const float xn = sx[nl];
                const float d0 = xn - tm0, d1 = xn - tm1;
                const float d0s = d0 * d0, d1s = d1 * d1;
                #pragma unroll
                for (int c4 = 0; c4 < CCH / 4; c4++) {
                    const float4 yv = sy[nl][c4];
                    #pragma unroll
                    for (int u = 0; u < 4; u++) {
                        const int c = c4 * 4 + u;
                        const float yu = (u == 0) ? yv.x : (u == 1) ? yv.y :
                                         (u == 2) ? yv.z : yv.w;
                        acc[0][c] += ex2f(q[c] * d0s) * yu;
                        acc[1][c] += ex2f(q[c] * d1s) * yu;
                    }
                }
            }
        }
    }

    // ---- epilogue: in-block n-reduce, then 16->32 linear ----
    __syncthreads();
    #pragma unroll
    for (int c = 0; c < CCH; c++) {
        sred[c][nsub][mslot]      = acc[0][c];
        sred[c][nsub][mslot + 16] = acc[1][c];
    }
    __syncthreads();

    // reduce over nsub: 512 sums, 4 per thread; lanes sweep m -> conflict-free
    #pragma unroll
    for (int r = 0; r < 4; r++) {
        const int idx = tid + THREADS * r;   // 0..511
        const int c = idx >> 5, m = idx & 31;
        float s = 0.0f;
        #pragma unroll
        for (int u = 0; u < NSUB; u++) s += sred[c][u][m];
        yout[m][c] = s;
    }
    __syncthreads();

    // linear: 32m x 32o outputs, 8 per thread
    const int m_l = tid >> 2;
    const int ob  = (tid & 3) * 8;
    float yv[CCH];
    #pragma unroll
    for (int c = 0; c < CCH; c++) yv[c] = yout[m_l][c];

    float res[8];
    #pragma unroll
    for (int j = 0; j < 8; j++) {
        const int o = ob + j;
        float a = sb[o];
        #pragma unroll
        for (int c = 0; c < CCH; c++) a += yv[c] * sWt[c][o];
        res[j] = a;
    }
    float4* op = (float4*)(out + (((size_t)b * MOUT + mbase + m_l) * OCH) + ob);
    op[0] = make_float4(res[0], res[1], res[2], res[3]);
    op[1] = make_float4(res[4], res[5], res[6], res[7]);
}

extern "C" void kernel_launch(void* const* d_in, const int* in_sizes, int n_in,
                              void* d_out, int out_size)
{
    const float* x     = (const float*)d_in[0];
    const float* y     = (const float*)d_in[1];
    const float* t     = (const float*)d_in[2];
    const float* sigma = (const float*)d_in[3];
    const float* W     = (const float*)d_in[4];
    const float* bias  = (const float*)d_in[5];
    float* out = (float*)d_out;

    setconv_fused_kernel<<<BATCH * MTILES, THREADS>>>(x, y, t, sigma, W, bias, out);
}

// round 3
// speedup vs baseline: 1.1529x; 1.0078x over previous
#include <cuda_runtime.h>

#define BATCH 8
#define NOBS 1024
#define MOUT 1024
#define CCH 16
#define OCH 32
#define THREADS 128
#define M_B 16                     // m per block
#define MTILES (MOUT / M_B)        // 64  -> grid 512
#define CHUNK 128                  // n staged per chunk
#define NCHUNKS (NOBS / CHUNK)     // 8
#define NSUB 32                    // n-parallel threads
#define M_T 4                      // m per thread
#define NITER (CHUNK / NSUB)       // 4

__device__ __forceinline__ float ex2f(float v) {
    float r;
    asm("ex2.approx.ftz.f32 %0, %1;" : "=f"(r) : "f"(v));
    return r;
}

__global__ __launch_bounds__(THREADS, 4) void setconv_fused_kernel(
    const float* __restrict__ x, const float* __restrict__ y,
    const float* __restrict__ t, const float* __restrict__ sigma,
    const float* __restrict__ W, const float* __restrict__ bias,
    float* __restrict__ out)
{
    // sred (epilogue) aliases sx/sy (mainloop) — never live simultaneously
    __shared__ union {
        struct {
            float  sx[CHUNK];
            float4 sy[CHUNK][5];          // 5 float4 = 80B row (20-bank stride), 4 used
        } ml;
        float sred[CCH][NSUB][M_B];       // 32 KB
    } u;
    __shared__ float yout[M_B][CCH + 1];
    __shared__ float sWt[CCH][OCH];
    __shared__ float sb[OCH];

    const int tid   = threadIdx.x;
    const int b     = blockIdx.x / MTILES;
    const int mt    = blockIdx.x % MTILES;
    const int nsub  = tid >> 2;     // 0..31 (8 distinct per warp -> padded rows conflict-free)
    const int mslot = tid & 3;      // 0..3

    // stage W transposed + bias
    for (int i = tid; i < OCH * CCH; i += THREADS) {
        int o = i / CCH, c = i % CCH;
        sWt[c][o] = W[i];
    }
    if (tid < OCH) sb[tid] = bias[tid];

    // uniform-sigma fast path check (true here: sigma = full(log 0.1))
    const float sg0 = sigma[0];
    bool uniform = true;
    #pragma unroll
    for (int c = 1; c < CCH; c++) uniform &= (sigma[c] == sg0);
    // q = -0.5*log2(e)/s^2, s = exp(sigma)
    const float q0 = -0.72134752044448170f * ex2f(-2.0f * sg0 * 1.4426950408889634f);

    const int mbase = mt * M_B;
    float tm[M_T];
    #pragma unroll
    for (int k = 0; k < M_T; k++)
        tm[k] = t[b * MOUT + mbase + k * 4 + mslot];

    float acc[M_T][CCH];
    #pragma unroll
    for (int k = 0; k < M_T; k++)
        #pragma unroll
        for (int c = 0; c < CCH; c++) acc[k][c] = 0.0f;

    for (int ch = 0; ch < NCHUNKS; ch++) {
        __syncthreads();
        const int n0 = ch * CHUNK;
        u.ml.sx[tid] = x[b * NOBS + n0 + tid];
        {
            const float4* y4 = (const float4*)(y + ((size_t)b * NOBS + n0) * CCH);
            #pragma unroll
            for (int r = 0; r < CHUNK * 4 / THREADS; r++) {  // 4 rounds of 128
                int i = tid + THREADS * r;                   // flat float4 idx
                u.ml.sy[i >> 2][i & 3] = y4[i];
            }
        }
        __syncthreads();

        if (uniform) {
            #pragma unroll
            for (int i = 0; i < NITER; i++) {
                const int nl = i * NSUB + nsub;
                const float xn = u.ml.sx[nl];
                float w[M_T];
                #pragma unroll
                for (int k = 0; k < M_T; k++) {
                    float d = xn - tm[k];
                    w[k] = ex2f(q0 * d * d);
                }
                #pragma unroll
                for (int c4 = 0; c4 < CCH / 4; c4++) {
                    const float4 yv = u.ml.sy[nl][c4];
                    #pragma unroll
                    for (int k = 0; k < M_T; k++) {
                        acc[k][c4*4+0] += w[k] * yv.x;
                        acc[k][c4*4+1] += w[k] * yv.y;
                        acc[k][c4*4+2] += w[k] * yv.z;
                        acc[k][c4*4+3] += w[k] * yv.w;
                    }
                }
            }
        } else {
            float q[CCH];
            #pragma unroll
            for (int c = 0; c < CCH; c++)
                q[c] = -0.72134752044448170f *
                       ex2f(-2.0f * sigma[c] * 1.4426950408889634f);
            for (int i = 0; i < NITER; i++) {
                const int nl = i * NSUB + nsub;
                const float xn = u.ml.sx[nl];
                float ds[M_T];
                #pragma unroll
                for (int k = 0; k < M_T; k++) {
                    float d = xn - tm[k];
                    ds[k] = d * d;
                }
                #pragma unroll
                for (int c4 = 0; c4 < CCH / 4; c4++) {
                    const float4 yv = u.ml.sy[nl][c4];
                    #pragma unroll
                    for (int k = 0; k < M_T; k++) {
                        acc[k][c4*4+0] += ex2f(q[c4*4+0] * ds[k]) * yv.x;
                        acc[k][c4*4+1] += ex2f(q[c4*4+1] * ds[k]) * yv.y;
                        acc[k][c4*4+2] += ex2f(q[c4*4+2] * ds[k]) * yv.z;
                        acc[k][c4*4+3] += ex2f(q[c4*4+3] * ds[k]) * yv.w;
                    }
                }
            }
        }
    }

    // ---- epilogue: nsub-reduction + 16->32 linear ----
    __syncthreads();                 // sy dead; union becomes sred
    #pragma unroll
    for (int k = 0; k < M_T; k++)
        #pragma unroll
        for (int c = 0; c < CCH; c++)
            u.sred[c][nsub][k * 4 + mslot] = acc[k][c];
    __syncthreads();

    // 256 (c,m) sums over 32 nsub partials; 2 per thread
    #pragma unroll
    for (int r = 0; r < 2; r++) {
        const int idx = tid + THREADS * r;      // 0..255
        const int c = idx >> 4, m = idx & 15;
        float s = 0.0f;
        #pragma unroll
        for (int v = 0; v < NSUB; v++) s += u.sred[c][v][m];
        yout[m][c] = s;
    }
    __syncthreads();

    // linear: 16m x 32o, 4 outputs per thread (float4 coalesced store)
    const int m_l = tid >> 3;           // 0..15
    const int ob  = (tid & 7) * 4;      // 0,4,...,28
    float yv[CCH];
    #pragma unroll
    for (int c = 0; c < CCH; c++) yv[c] = yout[m_l][c];

    float res[4];
    #pragma unroll
    for (int j = 0; j < 4; j++) {
        const int o = ob + j;
        float a = sb[o];
        #pragma unroll
        for (int c = 0; c < CCH; c++) a += yv[c] * sWt[c][o];
        res[j] = a;
    }
    *(float4*)(out + (((size_t)b * MOUT + mbase + m_l) * OCH) + ob) =
        make_float4(res[0], res[1], res[2], res[3]);
}

extern "C" void kernel_launch(void* const* d_in, const int* in_sizes, int n_in,
                              void* d_out, int out_size)
{
    const float* x     = (const float*)d_in[0];
    const float* y     = (const float*)d_in[1];
    const float* t     = (const float*)d_in[2];
    const float* sigma = (const float*)d_in[3];
    const float* W     = (const float*)d_in[4];
    const float* bias  = (const float*)d_in[5];
    float* out = (float*)d_out;

    setconv_fused_kernel<<<BATCH * MTILES, THREADS>>>(x, y, t, sigma, W, bias, out);
}

// round 4
// speedup vs baseline: 1.6350x; 1.4181x over previous
#include <cuda_runtime.h>
#include <cuda_fp16.h>
#include <cstdint>

#define BATCH 8
#define NOBS 1024
#define MOUT 1024
#define CCH 16
#define OCH 32
#define THREADS 256
#define M_B 32
#define MTILES (MOUT / M_B)     // 32 -> grid 256
#define KSPLIT 4
#define KPW (NOBS / KSPLIT)     // 256 per warp
#define KTILES (KPW / 16)       // 16 k-tiles
#define ROWH 40                 // halves per y row: 16 hi + 16 lo + 8 pad = 80B

struct MLBuf {
    float  sx[NOBS];                       // 4 KB
    __align__(16) __half syhl[NOBS][ROWH]; // 80 KB
};
union SMem {
    MLBuf ml;
    float sred[2][KSPLIT][16][16];         // 8 KB (epilogue, aliases mainloop bufs)
};
#define DYN_SMEM_BYTES ((int)sizeof(SMem))

__device__ __forceinline__ float ex2f(float v) {
    float r; asm("ex2.approx.ftz.f32 %0, %1;" : "=f"(r) : "f"(v)); return r;
}
__device__ __forceinline__ uint32_t s2u(const void* p) {
    return (uint32_t)__cvta_generic_to_shared(p);
}
// pack two f32 -> f16x2, lo in low half
__device__ __forceinline__ uint32_t packh2(float lo, float hi) {
    uint32_t r; asm("cvt.rn.f16x2.f32 %0, %1, %2;" : "=r"(r) : "f"(hi), "f"(lo)); return r;
}
__device__ __forceinline__ void ldm_x4_t(uint32_t& r0, uint32_t& r1, uint32_t& r2,
                                         uint32_t& r3, uint32_t addr) {
    asm volatile("ldmatrix.sync.aligned.m8n8.x4.trans.shared.b16 {%0,%1,%2,%3}, [%4];"
                 : "=r"(r0), "=r"(r1), "=r"(r2), "=r"(r3) : "r"(addr));
}
__device__ __forceinline__ void mma16816(float& c0, float& c1, float& c2, float& c3,
                                         uint32_t a0, uint32_t a1, uint32_t a2, uint32_t a3,
                                         uint32_t b0, uint32_t b1) {
    asm volatile("mma.sync.aligned.m16n8k16.row.col.f32.f16.f16.f32 "
                 "{%0,%1,%2,%3}, {%4,%5,%6,%7}, {%8,%9}, {%0,%1,%2,%3};"
                 : "+f"(c0), "+f"(c1), "+f"(c2), "+f"(c3)
                 : "r"(a0), "r"(a1), "r"(a2), "r"(a3), "r"(b0), "r"(b1));
}

__global__ void setconv_mma_kernel(
    const float* __restrict__ x, const float* __restrict__ y,
    const float* __restrict__ t, const float* __restrict__ sigma,
    const float* __restrict__ W, const float* __restrict__ bias,
    float* __restrict__ out)
{
    extern __shared__ __align__(16) unsigned char dynsm[];
    SMem& u = *reinterpret_cast<SMem*>(dynsm);
    __shared__ float sWt[CCH][OCH];
    __shared__ float sb[OCH];
    __shared__ float yout[M_B][CCH + 1];

    const int tid  = threadIdx.x;
    const int warp = tid >> 5, lane = tid & 31;
    const int b  = blockIdx.x / MTILES;
    const int mt = blockIdx.x % MTILES;
    const int mbase = mt * M_B;
    const int mg = warp >> 2;      // m-group 0..1 (16 m each)
    const int ks = warp & 3;       // k-split 0..3 (256 n each)

    // ---- stage x, y(hi/lo f16), W, bias ----
    for (int i = tid; i < NOBS; i += THREADS) u.ml.sx[i] = x[b * NOBS + i];
    {
        const float4* yb = (const float4*)(y + (size_t)b * NOBS * CCH);
        #pragma unroll
        for (int r = 0; r < NOBS * CCH / 4 / THREADS; r++) {   // 16 rounds
            int j = tid + THREADS * r;
            int n = j >> 2, c4 = j & 3;
            float4 v = yb[j];
            __half2 h0 = __floats2half2_rn(v.x, v.y);
            __half2 h1 = __floats2half2_rn(v.z, v.w);
            float2 f0 = __half22float2(h0), f1 = __half22float2(h1);
            __half2 l0 = __floats2half2_rn(v.x - f0.x, v.y - f0.y);
            __half2 l1 = __floats2half2_rn(v.z - f1.x, v.w - f1.y);
            __half2* row = (__half2*)&u.ml.syhl[n][0];
            row[c4 * 2]     = h0;  row[c4 * 2 + 1]     = h1;
            row[8 + c4 * 2] = l0;  row[8 + c4 * 2 + 1] = l1;
        }
    }
    for (int i = tid; i < OCH * CCH; i += THREADS) {
        int o = i / CCH, c = i % CCH;
        sWt[c][o] = W[i];
    }
    if (tid < OCH) sb[tid] = bias[tid];

    const float sg0 = sigma[0];
    bool uniform = true;
    #pragma unroll
    for (int c = 1; c < CCH; c++) uniform &= (sigma[c] == sg0);
    const float q0 = -0.72134752044448170f * ex2f(-2.0f * sg0 * 1.4426950408889634f);

    __syncthreads();

    if (uniform) {
        const int g  = lane >> 2;        // 0..7
        const int tq = lane & 3;         // 0..3
        const float t0 = t[b * MOUT + mbase + mg * 16 + g];
        const float t1 = t[b * MOUT + mbase + mg * 16 + g + 8];

        float c00 = 0.f, c01 = 0.f, c02 = 0.f, c03 = 0.f;   // channels 0-7
        float c10 = 0.f, c11 = 0.f, c12 = 0.f, c13 = 0.f;   // channels 8-15

        // ldmatrix lane address: rows k0+(lane&15), col half (lane&16)
        const uint32_t lmbase = s2u(&u.ml.syhl[lane & 15][0]) + ((lane & 16) ? 16u : 0u);
        const int kbase = ks * KPW;

        #pragma unroll 2
        for (int kt = 0; kt < KTILES; kt++) {
            const int k0 = kbase + kt * 16;
            const float2 xa = *(const float2*)&u.ml.sx[k0 + 2 * tq];
            const float2 xb = *(const float2*)&u.ml.sx[k0 + 2 * tq + 8];

            float d;
            d = xa.x - t0; const float w00 = ex2f(q0 * d * d);
            d = xa.y - t0; const float w01 = ex2f(q0 * d * d);
            d = xa.x - t1; const float w10 = ex2f(q0 * d * d);
            d = xa.y - t1; const float w11 = ex2f(q0 * d * d);
            d = xb.x - t0; const float w02 = ex2f(q0 * d * d);
            d = xb.y - t0; const float w03 = ex2f(q0 * d * d);
            d = xb.x - t1; const float w12 = ex2f(q0 * d * d);
            d = xb.y - t1; const float w13 = ex2f(q0 * d * d);

            const uint32_t ah0 = packh2(w00, w01);
            const uint32_t ah1 = packh2(w10, w11);
            const uint32_t ah2 = packh2(w02, w03);
            const uint32_t ah3 = packh2(w12, w13);
            // w residual (A lo plane)
            float2 f;
            f = __half22float2(*(const __half2*)&ah0);
            const uint32_t al0 = packh2(w00 - f.x, w01 - f.y);
            f = __half22float2(*(const __half2*)&ah1);
            const uint32_t al1 = packh2(w10 - f.x, w11 - f.y);
            f = __half22float2(*(const __half2*)&ah2);
            const uint32_t al2 = packh2(w02 - f.x, w03 - f.y);
            f = __half22float2(*(const __half2*)&ah3);
            const uint32_t al3 = packh2(w12 - f.x, w13 - f.y);

            const uint32_t addr = lmbase + (uint32_t)k0 * (ROWH * 2);
            uint32_t bh0, bh1, bh2, bh3, bl0, bl1, bl2, bl3;
            ldm_x4_t(bh0, bh1, bh2, bh3, addr);        // y hi plane
            ldm_x4_t(bl0, bl1, bl2, bl3, addr + 32);   // y lo plane

            // C += wh*yh + wh*yl + wl*yh
            mma16816(c00, c01, c02, c03, ah0, ah1, ah2, ah3, bh0, bh1);
            mma16816(c00, c01, c02, c03, ah0, ah1, ah2, ah3, bl0, bl1);
            mma16816(c00, c01, c02, c03, al0, al1, al2, al3, bh0, bh1);
            mma16816(c10, c11, c12, c13, ah0, ah1, ah2, ah3, bh2, bh3);
            mma16816(c10, c11, c12, c13, ah0, ah1, ah2, ah3, bl2, bl3);
            mma16816(c10, c11, c12, c13, al0, al1, al2, al3, bh2, bh3);
        }

        __syncthreads();   // all warps done with sx/syhl; union becomes sred
        const int col0 = 2 * tq;
        *(float2*)&u.sred[mg][ks][g][col0]          = make_float2(c00, c01);
        *(float2*)&u.sred[mg][ks][g + 8][col0]      = make_float2(c02, c03);
        *(float2*)&u.sred[mg][ks][g][8 + col0]      = make_float2(c10, c11);
        *(float2*)&u.sred[mg][ks][g + 8][8 + col0]  = make_float2(c12, c13);
    } else {
        // ---- general per-channel-sigma fallback (slow, correct) ----
        float q[CCH];
        #pragma unroll
        for (int c = 0; c < CCH; c++)
            q[c] = -0.72134752044448170f * ex2f(-2.0f * sigma[c] * 1.4426950408889634f);
        const int ml = lane & 15;
        const int half = lane >> 4;
        const float tm = t[b * MOUT + mbase + mg * 16 + ml];
        float acc[CCH];
        #pragma unroll
        for (int c = 0; c < CCH; c++) acc[c] = 0.0f;
        for (int nn = ks * KPW + half; nn < (ks + 1) * KPW; nn += 2) {
            const float xv = u.ml.sx[nn];
            const float dd = (xv - tm) * (xv - tm);
            const __half2* row = (const __half2*)&u.ml.syhl[nn][0];
            #pragma unroll
            for (int c2 = 0; c2 < 8; c2++) {
                const float2 yh = __half22float2(row[c2]);
                const float2 yl = __half22float2(row[8 + c2]);
                acc[2 * c2]     += ex2f(q[2 * c2] * dd) * (yh.x + yl.x);
                acc[2 * c2 + 1] += ex2f(q[2 * c2 + 1] * dd) * (yh.y + yl.y);
            }
        }
        #pragma unroll
        for (int c = 0; c < CCH; c++)
            acc[c] += __shfl_xor_sync(0xffffffffu, acc[c], 16);
        __syncthreads();
        if (half == 0)
            #pragma unroll
            for (int c = 0; c < CCH; c++) u.sred[mg][ks][ml][c] = acc[c];
    }

    __syncthreads();

    // ---- reduce 4 k-splits -> yout ----
    #pragma unroll
    for (int r = 0; r < 2; r++) {
        const int idx = tid + THREADS * r;      // 0..511
        const int mgi = idx >> 8;
        const int m   = (idx >> 4) & 15;
        const int c   = idx & 15;
        float s = 0.0f;
        #pragma unroll
        for (int k = 0; k < KSPLIT; k++) s += u.sred[mgi][k][m][c];
        yout[mgi * 16 + m][c] = s;
    }
    __syncthreads();

    // ---- 16->32 linear + store ----
    const int m_l = tid >> 3;           // 0..31
    const int ob  = (tid & 7) * 4;      // 0..28
    float yv[CCH];
    #pragma unroll
    for (int c = 0; c < CCH; c++) yv[c] = yout[m_l][c];
    float res[4];
    #pragma unroll
    for (int j = 0; j < 4; j++) {
        const int o = ob + j;
        float a = sb[o];
        #pragma unroll
        for (int c = 0; c < CCH; c++) a += yv[c] * sWt[c][o];
        res[j] = a;
    }
    *(float4*)(out + (((size_t)b * MOUT + mbase + m_l) * OCH) + ob) =
        make_float4(res[0], res[1], res[2], res[3]);
}

extern "C" void kernel_launch(void* const* d_in, const int* in_sizes, int n_in,
                              void* d_out, int out_size)
{
    const float* x     = (const float*)d_in[0];
    const float* y     = (const float*)d_in[1];
    const float* t     = (const float*)d_in[2];
    const float* sigma = (const float*)d_in[3];
    const float* W     = (const float*)d_in[4];
    const float* bias  = (const float*)d_in[5];
    float* out = (float*)d_out;

    cudaFuncSetAttribute(setconv_mma_kernel,
                         cudaFuncAttributeMaxDynamicSharedMemorySize, DYN_SMEM_BYTES);
    setconv_mma_kernel<<<BATCH * MTILES, THREADS, DYN_SMEM_BYTES>>>(
        x, y, t, sigma, W, bias, out);
}

// round 5
// speedup vs baseline: 1.7067x; 1.0439x over previous
#include <cuda_runtime.h>
#include <cuda_fp16.h>
#include <cstdint>
#include <math.h>

#define BATCH 8
#define NOBS 1024
#define MOUT 1024
#define CCH 16
#define OCH 32
#define THREADS 512
#define M_B 32
#define MTILES (MOUT / M_B)     // 32 -> grid 256
#define KSPLIT 8
#define KPW (NOBS / KSPLIT)     // 128 per warp
#define KTILES (KPW / 16)       // 8 k-tiles
#define ROWH 40                 // halves per y row: 16 hi + 16 lo + 8 pad = 80B

struct MLBuf {
    float  sx[NOBS];                       // 4 KB (scaled by s in uniform mode)
    __align__(16) __half syhl[NOBS][ROWH]; // 80 KB
};
union SMem {
    MLBuf ml;
    float sred[2][KSPLIT][16][16];         // 16 KB (epilogue, aliases mainloop bufs)
};
#define DYN_SMEM_BYTES ((int)sizeof(SMem))

__device__ __forceinline__ float ex2f(float v) {
    float r; asm("ex2.approx.ftz.f32 %0, %1;" : "=f"(r) : "f"(v)); return r;
}
__device__ __forceinline__ uint32_t s2u(const void* p) {
    return (uint32_t)__cvta_generic_to_shared(p);
}
__device__ __forceinline__ uint32_t packh2(float lo, float hi) {
    uint32_t r; asm("cvt.rn.f16x2.f32 %0, %1, %2;" : "=r"(r) : "f"(hi), "f"(lo)); return r;
}
__device__ __forceinline__ void ldm_x4_t(uint32_t& r0, uint32_t& r1, uint32_t& r2,
                                         uint32_t& r3, uint32_t addr) {
    asm volatile("ldmatrix.sync.aligned.m8n8.x4.trans.shared.b16 {%0,%1,%2,%3}, [%4];"
                 : "=r"(r0), "=r"(r1), "=r"(r2), "=r"(r3) : "r"(addr));
}
__device__ __forceinline__ void mma16816(float& c0, float& c1, float& c2, float& c3,
                                         uint32_t a0, uint32_t a1, uint32_t a2, uint32_t a3,
                                         uint32_t b0, uint32_t b1) {
    asm volatile("mma.sync.aligned.m16n8k16.row.col.f32.f16.f16.f32 "
                 "{%0,%1,%2,%3}, {%4,%5,%6,%7}, {%8,%9}, {%0,%1,%2,%3};"
                 : "+f"(c0), "+f"(c1), "+f"(c2), "+f"(c3)
                 : "r"(a0), "r"(a1), "r"(a2), "r"(a3), "r"(b0), "r"(b1));
}

__global__ __launch_bounds__(THREADS, 2) void setconv_mma_kernel(
    const float* __restrict__ x, const float* __restrict__ y,
    const float* __restrict__ t, const float* __restrict__ sigma,
    const float* __restrict__ W, const float* __restrict__ bias,
    float* __restrict__ out)
{
    extern __shared__ __align__(16) unsigned char dynsm[];
    SMem& u = *reinterpret_cast<SMem*>(dynsm);
    __shared__ float sWt[CCH][OCH];
    __shared__ float sb[OCH];
    __shared__ float yout[M_B][CCH + 1];

    const int tid  = threadIdx.x;
    const int warp = tid >> 5, lane = tid & 31;
    const int b  = blockIdx.x / MTILES;
    const int mt = blockIdx.x % MTILES;
    const int mbase = mt * M_B;
    const int mg = warp >> 3;      // m-group 0..1 (16 m each)
    const int ks = warp & 7;       // k-split 0..7 (128 n each)

    // uniform-sigma check before staging (x is stored pre-scaled in uniform mode)
    const float sg0 = sigma[0];
    bool uniform = true;
    #pragma unroll
    for (int c = 1; c < CCH; c++) uniform &= (sigma[c] == sg0);
    // q0 = -0.5*log2(e)/s^2; scl = sqrt(-q0) so exp2(q0*d^2) = exp2(-(scl*d)^2)
    const float q0  = -0.72134752044448170f * ex2f(-2.0f * sg0 * 1.4426950408889634f);
    const float scl = sqrtf(-q0);

    // ---- stage x (scaled), y(hi/lo f16), W, bias ----
    {
        const float xs = uniform ? scl : 1.0f;
        for (int i = tid; i < NOBS; i += THREADS)
            u.ml.sx[i] = xs * x[b * NOBS + i];
    }
    {
        const float4* yb = (const float4*)(y + (size_t)b * NOBS * CCH);
        #pragma unroll
        for (int r = 0; r < NOBS * CCH / 4 / THREADS; r++) {   // 8 rounds
            int j = tid + THREADS * r;
            int n = j >> 2, c4 = j & 3;
            float4 v = yb[j];
            __half2 h0 = __floats2half2_rn(v.x, v.y);
            __half2 h1 = __floats2half2_rn(v.z, v.w);
            float2 f0 = __half22float2(h0), f1 = __half22float2(h1);
            __half2 l0 = __floats2half2_rn(v.x - f0.x, v.y - f0.y);
            __half2 l1 = __floats2half2_rn(v.z - f1.x, v.w - f1.y);
            __half2* row = (__half2*)&u.ml.syhl[n][0];
            row[c4 * 2]     = h0;  row[c4 * 2 + 1]     = h1;
            row[8 + c4 * 2] = l0;  row[8 + c4 * 2 + 1] = l1;
        }
    }
    for (int i = tid; i < OCH * CCH; i += THREADS) {
        int o = i / CCH, c = i % CCH;
        sWt[c][o] = W[i];
    }
    if (tid < OCH) sb[tid] = bias[tid];

    __syncthreads();

    if (uniform) {
        const int g  = lane >> 2;        // 0..7
        const int tq = lane & 3;         // 0..3
        const float t0 = scl * t[b * MOUT + mbase + mg * 16 + g];
        const float t1 = scl * t[b * MOUT + mbase + mg * 16 + g + 8];

        float c00 = 0.f, c01 = 0.f, c02 = 0.f, c03 = 0.f;   // channels 0-7
        float c10 = 0.f, c11 = 0.f, c12 = 0.f, c13 = 0.f;   // channels 8-15

        const uint32_t lmbase = s2u(&u.ml.syhl[lane & 15][0]) + ((lane & 16) ? 16u : 0u);
        const int kbase = ks * KPW;

        #pragma unroll 2
        for (int kt = 0; kt < KTILES; kt++) {
            const int k0 = kbase + kt * 16;
            const float2 xa = *(const float2*)&u.ml.sx[k0 + 2 * tq];
            const float2 xb = *(const float2*)&u.ml.sx[k0 + 2 * tq + 8];

            float d;
            d = xa.x - t0; const float w00 = ex2f(-d * d);
            d = xa.y - t0; const float w01 = ex2f(-d * d);
            d = xa.x - t1; const float w10 = ex2f(-d * d);
            d = xa.y - t1; const float w11 = ex2f(-d * d);
            d = xb.x - t0; const float w02 = ex2f(-d * d);
            d = xb.y - t0; const float w03 = ex2f(-d * d);
            d = xb.x - t1; const float w12 = ex2f(-d * d);
            d = xb.y - t1; const float w13 = ex2f(-d * d);

            const uint32_t ah0 = packh2(w00, w01);
            const uint32_t ah1 = packh2(w10, w11);
            const uint32_t ah2 = packh2(w02, w03);
            const uint32_t ah3 = packh2(w12, w13);
            float2 f;
            f = __half22float2(*(const __half2*)&ah0);
            const uint32_t al0 = packh2(w00 - f.x, w01 - f.y);
            f = __half22float2(*(const __half2*)&ah1);
            const uint32_t al1 = packh2(w10 - f.x, w11 - f.y);
            f = __half22float2(*(const __half2*)&ah2);
            const uint32_t al2 = packh2(w02 - f.x, w03 - f.y);
            f = __half22float2(*(const __half2*)&ah3);
            const uint32_t al3 = packh2(w12 - f.x, w13 - f.y);

            const uint32_t addr = lmbase + (uint32_t)k0 * (ROWH * 2);
            uint32_t bh0, bh1, bh2, bh3, bl0, bl1, bl2, bl3;
            ldm_x4_t(bh0, bh1, bh2, bh3, addr);        // y hi plane
            ldm_x4_t(bl0, bl1, bl2, bl3, addr + 32);   // y lo plane

            // C += wh*yh + wh*yl + wl*yh
            mma16816(c00, c01, c02, c03, ah0, ah1, ah2, ah3, bh0, bh1);
            mma16816(c00, c01, c02, c03, ah0, ah1, ah2, ah3, bl0, bl1);
            mma16816(c00, c01, c02, c03, al0, al1, al2, al3, bh0, bh1);
            mma16816(c10, c11, c12, c13, ah0, ah1, ah2, ah3, bh2, bh3);
            mma16816(c10, c11, c12, c13, ah0, ah1, ah2, ah3, bl2, bl3);
            mma16816(c10, c11, c12, c13, al0, al1, al2, al3, bh2, bh3);
        }

        __syncthreads();   // mainloop buffers dead; union becomes sred
        const int col0 = 2 * tq;
        *(float2*)&u.sred[mg][ks][g][col0]          = make_float2(c00, c01);
        *(float2*)&u.sred[mg][ks][g + 8][col0]      = make_float2(c02, c03);
        *(float2*)&u.sred[mg][ks][g][8 + col0]      = make_float2(c10, c11);
        *(float2*)&u.sred[mg][ks][g + 8][8 + col0]  = make_float2(c12, c13);
    } else {
        // ---- general per-channel-sigma fallback (slow, correct) ----
        float q[CCH];
        #pragma unroll
        for (int c = 0; c < CCH; c++)
            q[c] = -0.72134752044448170f * ex2f(-2.0f * sigma[c] * 1.4426950408889634f);
        const int ml = lane & 15;
        const int half = lane >> 4;
        const float tm = t[b * MOUT + mbase + mg * 16 + ml];
        float acc[CCH];
        #pragma unroll
        for (int c = 0; c < CCH; c++) acc[c] = 0.0f;
        for (int nn = ks * KPW + half; nn < (ks + 1) * KPW; nn += 2) {
            const float xv = u.ml.sx[nn];
            const float dd = (xv - tm) * (xv - tm);
            const __half2* row = (const __half2*)&u.ml.syhl[nn][0];
            #pragma unroll
            for (int c2 = 0; c2 < 8; c2++) {
                const float2 yh = __half22float2(row[c2]);
                const float2 yl = __half22float2(row[8 + c2]);
                acc[2 * c2]     += ex2f(q[2 * c2] * dd) * (yh.x + yl.x);
                acc[2 * c2 + 1] += ex2f(q[2 * c2 + 1] * dd) * (yh.y + yl.y);
            }
        }
        #pragma unroll
        for (int c = 0; c < CCH; c++)
            acc[c] += __shfl_xor_sync(0xffffffffu, acc[c], 16);
        __syncthreads();
        if (half == 0)
            #pragma unroll
            for (int c = 0; c < CCH; c++) u.sred[mg][ks][ml][c] = acc[c];
    }

    __syncthreads();

    // ---- reduce 8 k-splits -> yout (512 sums, 1 per thread) ----
    {
        const int mgi = tid >> 8;
        const int m   = (tid >> 4) & 15;
        const int c   = tid & 15;
        float s = 0.0f;
        #pragma unroll
        for (int k = 0; k < KSPLIT; k++) s += u.sred[mgi][k][m][c];
        yout[mgi * 16 + m][c] = s;
    }
    __syncthreads();

    // ---- 16->32 linear + store (1024 outputs, 2 per thread) ----
    const int m_l = tid >> 4;           // 0..31
    const int ob  = (tid & 15) * 2;     // 0..30
    float yv[CCH];
    #pragma unroll
    for (int c = 0; c < CCH; c++) yv[c] = yout[m_l][c];
    float res[2];
    #pragma unroll
    for (int j = 0; j < 2; j++) {
        const int o = ob + j;
        float a = sb[o];
        #pragma unroll
        for (int c = 0; c < CCH; c++) a += yv[c] * sWt[c][o];
        res[j] = a;
    }
    *(float2*)(out + (((size_t)b * MOUT + mbase + m_l) * OCH) + ob) =
        make_float2(res[0], res[1]);
}

extern "C" void kernel_launch(void* const* d_in, const int* in_sizes, int n_in,
                              void* d_out, int out_size)
{
    const float* x     = (const float*)d_in[0];
    const float* y     = (const float*)d_in[1];
    const float* t     = (const float*)d_in[2];
    const float* sigma = (const float*)d_in[3];
    const float* W     = (const float*)d_in[4];
    const float* bias  = (const float*)d_in[5];
    float* out = (float*)d_out;

    cudaFuncSetAttribute(setconv_mma_kernel,
                         cudaFuncAttributeMaxDynamicSharedMemorySize, DYN_SMEM_BYTES);
    setconv_mma_kernel<<<BATCH * MTILES, THREADS, DYN_SMEM_BYTES>>>(
        x, y, t, sigma, W, bias, out);
}

// round 6
// speedup vs baseline: 1.8429x; 1.0798x over previous
#include <cuda_runtime.h>
#include <cuda_fp16.h>
#include <cstdint>
#include <math.h>

#define BATCH 8
#define NOBS 1024
#define MOUT 1024
#define CCH 16
#define OCH 32
#define THREADS 512
#define M_B 32
#define MTILES (MOUT / M_B)     // 32 -> grid 256
#define KSPLIT 8
#define KPW (NOBS / KSPLIT)     // 128 per warp
#define KTILES (KPW / 16)       // 8 k-tiles
#define ROWH 40                 // halves per y row: 16 hi + 16 lo + 8 pad = 80B
#define ROWB (ROWH * 2)         // 80 bytes per row

struct MLBuf {
    float  sx[NOBS];                       // 4 KB (scaled by s in uniform mode)
    __align__(16) __half syhl[NOBS][ROWH]; // 80 KB
};
union SMem {
    MLBuf ml;
    float sred[2][KSPLIT][16][16];         // 16 KB (epilogue, aliases mainloop bufs)
};
#define DYN_SMEM_BYTES ((int)sizeof(SMem))

__device__ __forceinline__ float ex2f(float v) {
    float r; asm("ex2.approx.ftz.f32 %0, %1;" : "=f"(r) : "f"(v)); return r;
}
__device__ __forceinline__ uint32_t s2u(const void* p) {
    return (uint32_t)__cvta_generic_to_shared(p);
}
__device__ __forceinline__ uint32_t packh2(float lo, float hi) {
    uint32_t r; asm("cvt.rn.f16x2.f32 %0, %1, %2;" : "=r"(r) : "f"(hi), "f"(lo)); return r;
}
__device__ __forceinline__ void ldm_x4_t(uint32_t& r0, uint32_t& r1, uint32_t& r2,
                                         uint32_t& r3, uint32_t addr) {
    asm volatile("ldmatrix.sync.aligned.m8n8.x4.trans.shared.b16 {%0,%1,%2,%3}, [%4];"
                 : "=r"(r0), "=r"(r1), "=r"(r2), "=r"(r3) : "r"(addr));
}
__device__ __forceinline__ void mma16816(float& c0, float& c1, float& c2, float& c3,
                                         uint32_t a0, uint32_t a1, uint32_t a2, uint32_t a3,
                                         uint32_t b0, uint32_t b1) {
    asm volatile("mma.sync.aligned.m16n8k16.row.col.f32.f16.f16.f32 "
                 "{%0,%1,%2,%3}, {%4,%5,%6,%7}, {%8,%9}, {%0,%1,%2,%3};"
                 : "+f"(c0), "+f"(c1), "+f"(c2), "+f"(c3)
                 : "r"(a0), "r"(a1), "r"(a2), "r"(a3), "r"(b0), "r"(b1));
}

__global__ __launch_bounds__(THREADS, 2) void setconv_mma_kernel(
    const float* __restrict__ x, const float* __restrict__ y,
    const float* __restrict__ t, const float* __restrict__ sigma,
    const float* __restrict__ W, const float* __restrict__ bias,
    float* __restrict__ out)
{
    extern __shared__ __align__(16) unsigned char dynsm[];
    SMem& u = *reinterpret_cast<SMem*>(dynsm);
    __shared__ float sWt[CCH][OCH];
    __shared__ float sb[OCH];
    __shared__ float yout[M_B][CCH + 1];

    const int tid  = threadIdx.x;
    const int warp = tid >> 5, lane = tid & 31;
    const int b  = blockIdx.x / MTILES;
    const int mt = blockIdx.x % MTILES;
    const int mbase = mt * M_B;
    const int mg = warp >> 3;      // m-group 0..1 (16 m each)
    const int ks = warp & 7;       // k-split 0..7 (128 n each)

    // uniform-sigma check before staging (x stored pre-scaled in uniform mode)
    const float sg0 = sigma[0];
    bool uniform = true;
    #pragma unroll
    for (int c = 1; c < CCH; c++) uniform &= (sigma[c] == sg0);
    // q0 = -0.5*log2(e)/s^2; scl = sqrt(-q0) so exp2(q0*d^2) = exp2(-(scl*d)^2)
    const float q0  = -0.72134752044448170f * ex2f(-2.0f * sg0 * 1.4426950408889634f);
    const float scl = sqrtf(-q0);

    // ---- stage x (scaled), y(hi/lo f16), W, bias ----
    {
        const float xs = uniform ? scl : 1.0f;
        for (int i = tid; i < NOBS; i += THREADS)
            u.ml.sx[i] = xs * x[b * NOBS + i];
    }
    {
        const float4* yb = (const float4*)(y + (size_t)b * NOBS * CCH);
        #pragma unroll
        for (int r = 0; r < NOBS * CCH / 4 / THREADS; r++) {   // 8 rounds
            int j = tid + THREADS * r;
            int n = j >> 2, c4 = j & 3;
            float4 v = yb[j];
            __half2 h0 = __floats2half2_rn(v.x, v.y);
            __half2 h1 = __floats2half2_rn(v.z, v.w);
            float2 f0 = __half22float2(h0), f1 = __half22float2(h1);
            __half2 l0 = __floats2half2_rn(v.x - f0.x, v.y - f0.y);
            __half2 l1 = __floats2half2_rn(v.z - f1.x, v.w - f1.y);
            __half2* row = (__half2*)&u.ml.syhl[n][0];
            row[c4 * 2]     = h0;  row[c4 * 2 + 1]     = h1;
            row[8 + c4 * 2] = l0;  row[8 + c4 * 2 + 1] = l1;
        }
    }
    for (int i = tid; i < OCH * CCH; i += THREADS) {
        int o = i / CCH, c = i % CCH;
        sWt[c][o] = W[i];
    }
    if (tid < OCH) sb[tid] = bias[tid];

    __syncthreads();

    if (uniform) {
        const int g  = lane >> 2;        // 0..7
        const int tq = lane & 3;         // 0..3
        const float t0 = scl * t[b * MOUT + mbase + mg * 16 + g];
        const float t1 = scl * t[b * MOUT + mbase + mg * 16 + g + 8];

        float c00 = 0.f, c01 = 0.f, c02 = 0.f, c03 = 0.f;   // channels 0-7
        float c10 = 0.f, c11 = 0.f, c12 = 0.f, c13 = 0.f;   // channels 8-15

        const int kbase = ks * KPW;
        // per-warp bases; per-ktile offsets become immediates under full unroll
        const float* sxw = &u.ml.sx[kbase + 2 * tq];
        const uint32_t lmw = s2u(&u.ml.syhl[kbase + (lane & 15)][0])
                           + ((lane & 16) ? 16u : 0u);

        // prologue: prefetch ktile 0
        float2 xa = *(const float2*)&sxw[0];
        float2 xb = *(const float2*)&sxw[8];
        uint32_t bh[4], bl[4];
        ldm_x4_t(bh[0], bh[1], bh[2], bh[3], lmw);
        ldm_x4_t(bl[0], bl[1], bl[2], bl[3], lmw + 32);

        #pragma unroll
        for (int kt = 0; kt < KTILES; kt++) {
            float2 nxa, nxb;
            uint32_t nbh[4], nbl[4];
            if (kt + 1 < KTILES) {
                nxa = *(const float2*)&sxw[(kt + 1) * 16];
                nxb = *(const float2*)&sxw[(kt + 1) * 16 + 8];
                const uint32_t a = lmw + (uint32_t)(kt + 1) * (16 * ROWB);
                ldm_x4_t(nbh[0], nbh[1], nbh[2], nbh[3], a);
                ldm_x4_t(nbl[0], nbl[1], nbl[2], nbl[3], a + 32);
            }

            float d;
            d = xa.x - t0; const float w00 = ex2f(-d * d);
            d = xa.y - t0; const float w01 = ex2f(-d * d);
            d = xa.x - t1; const float w10 = ex2f(-d * d);
            d = xa.y - t1; const float w11 = ex2f(-d * d);
            d = xb.x - t0; const float w02 = ex2f(-d * d);
            d = xb.y - t0; const float w03 = ex2f(-d * d);
            d = xb.x - t1; const float w12 = ex2f(-d * d);
            d = xb.y - t1; const float w13 = ex2f(-d * d);

            const uint32_t a0 = packh2(w00, w01);
            const uint32_t a1 = packh2(w10, w11);
            const uint32_t a2 = packh2(w02, w03);
            const uint32_t a3 = packh2(w12, w13);

            // C += w*(y_hi) + w*(y_lo)
            mma16816(c00, c01, c02, c03, a0, a1, a2, a3, bh[0], bh[1]);
            mma16816(c00, c01, c02, c03, a0, a1, a2, a3, bl[0], bl[1]);
            mma16816(c10, c11, c12, c13, a0, a1, a2, a3, bh[2], bh[3]);
            mma16816(c10, c11, c12, c13, a0, a1, a2, a3, bl[2], bl[3]);

            xa = nxa; xb = nxb;
            #pragma unroll
            for (int j = 0; j < 4; j++) { bh[j] = nbh[j]; bl[j] = nbl[j]; }
        }

        __syncthreads();   // mainloop buffers dead; union becomes sred
        const int col0 = 2 * tq;
        *(float2*)&u.sred[mg][ks][g][col0]          = make_float2(c00, c01);
        *(float2*)&u.sred[mg][ks][g + 8][col0]      = make_float2(c02, c03);
        *(float2*)&u.sred[mg][ks][g][8 + col0]      = make_float2(c10, c11);
        *(float2*)&u.sred[mg][ks][g + 8][8 + col0]  = make_float2(c12, c13);
    } else {
        // ---- general per-channel-sigma fallback (slow, correct) ----
        float q[CCH];
        #pragma unroll
        for (int c = 0; c < CCH; c++)
            q[c] = -0.72134752044448170f * ex2f(-2.0f * sigma[c] * 1.4426950408889634f);
        const int ml = lane & 15;
        const int half = lane >> 4;
        const float tm = t[b * MOUT + mbase + mg * 16 + ml];
        float acc[CCH];
        #pragma unroll
        for (int c = 0; c < CCH; c++) acc[c] = 0.0f;
        for (int nn = ks * KPW + half; nn < (ks + 1) * KPW; nn += 2) {
            const float xv = u.ml.sx[nn];
            const float dd = (xv - tm) * (xv - tm);
            const __half2* row = (const __half2*)&u.ml.syhl[nn][0];
            #pragma unroll
            for (int c2 = 0; c2 < 8; c2++) {
                const float2 yh = __half22float2(row[c2]);
                const float2 yl = __half22float2(row[8 + c2]);
                acc[2 * c2]     += ex2f(q[2 * c2] * dd) * (yh.x + yl.x);
                acc[2 * c2 + 1] += ex2f(q[2 * c2 + 1] * dd) * (yh.y + yl.y);
            }
        }
        #pragma unroll
        for (int c = 0; c < CCH; c++)
            acc[c] += __shfl_xor_sync(0xffffffffu, acc[c], 16);
        __syncthreads();
        if (half == 0)
            #pragma unroll
            for (int c = 0; c < CCH; c++) u.sred[mg][ks][ml][c] = acc[c];
    }

    __syncthreads();

    // ---- reduce 8 k-splits -> yout (512 sums, 1 per thread) ----
    {
        const int mgi = tid >> 8;
        const int m   = (tid >> 4) & 15;
        const int c   = tid & 15;
        float s = 0.0f;
        #pragma unroll
        for (int k = 0; k < KSPLIT; k++) s += u.sred[mgi][k][m][c];
        yout[mgi * 16 + m][c] = s;
    }
    __syncthreads();

    // ---- 16->32 linear + store (1024 outputs, 2 per thread) ----
    const int m_l = tid >> 4;           // 0..31
    const int ob  = (tid & 15) * 2;     // 0..30
    float yv[CCH];
    #pragma unroll
    for (int c = 0; c < CCH; c++) yv[c] = yout[m_l][c];
    float res[2];
    #pragma unroll
    for (int j = 0; j < 2; j++) {
        const int o = ob + j;
        float a = sb[o];
        #pragma unroll
        for (int c = 0; c < CCH; c++) a += yv[c] * sWt[c][o];
        res[j] = a;
    }
    *(float2*)(out + (((size_t)b * MOUT + mbase + m_l) * OCH) + ob) =
        make_float2(res[0], res[1]);
}

extern "C" void kernel_launch(void* const* d_in, const int* in_sizes, int n_in,
                              void* d_out, int out_size)
{
    const float* x     = (const float*)d_in[0];
    const float* y     = (const float*)d_in[1];
    const float* t     = (const float*)d_in[2];
    const float* sigma = (const float*)d_in[3];
    const float* W     = (const float*)d_in[4];
    const float* bias  = (const float*)d_in[5];
    float* out = (float*)d_out;

    cudaFuncSetAttribute(setconv_mma_kernel,
                         cudaFuncAttributeMaxDynamicSharedMemorySize, DYN_SMEM_BYTES);
    setconv_mma_kernel<<<BATCH * MTILES, THREADS, DYN_SMEM_BYTES>>>(
        x, y, t, sigma, W, bias, out);
}

// round 7
// speedup vs baseline: 1.9707x; 1.0693x over previous
#include <cuda_runtime.h>
#include <cuda_fp16.h>
#include <cstdint>
#include <math.h>

#define BATCH 8
#define NOBS 1024
#define MOUT 1024
#define CCH 16
#define OCH 32
#define THREADS 512
#define M_B 32
#define MTILES (MOUT / M_B)     // 32 -> grid 256
#define KSPLIT 8
#define KPW (NOBS / KSPLIT)     // 128 per warp
#define KTILES (KPW / 16)       // 8 k-tiles
#define ROWH 24                 // halves per y row: 16 data + 8 pad = 48B (16B-aligned rows)
#define ROWB (ROWH * 2)         // 48 bytes

__device__ __forceinline__ float ex2f(float v) {
    float r; asm("ex2.approx.ftz.f32 %0, %1;" : "=f"(r) : "f"(v)); return r;
}
__device__ __forceinline__ uint32_t s2u(const void* p) {
    return (uint32_t)__cvta_generic_to_shared(p);
}
__device__ __forceinline__ uint32_t packh2(float lo, float hi) {
    uint32_t r; asm("cvt.rn.f16x2.f32 %0, %1, %2;" : "=r"(r) : "f"(hi), "f"(lo)); return r;
}
__device__ __forceinline__ void ldm_x4_t(uint32_t& r0, uint32_t& r1, uint32_t& r2,
                                         uint32_t& r3, uint32_t addr) {
    asm volatile("ldmatrix.sync.aligned.m8n8.x4.trans.shared.b16 {%0,%1,%2,%3}, [%4];"
                 : "=r"(r0), "=r"(r1), "=r"(r2), "=r"(r3) : "r"(addr));
}
__device__ __forceinline__ void mma16816(float& c0, float& c1, float& c2, float& c3,
                                         uint32_t a0, uint32_t a1, uint32_t a2, uint32_t a3,
                                         uint32_t b0, uint32_t b1) {
    asm volatile("mma.sync.aligned.m16n8k16.row.col.f32.f16.f16.f32 "
                 "{%0,%1,%2,%3}, {%4,%5,%6,%7}, {%8,%9}, {%0,%1,%2,%3};"
                 : "+f"(c0), "+f"(c1), "+f"(c2), "+f"(c3)
                 : "r"(a0), "r"(a1), "r"(a2), "r"(a3), "r"(b0), "r"(b1));
}

struct SMem {
    float  sx[NOBS];                        // 4 KB (scaled by s in uniform mode)
    __align__(16) __half syh[NOBS][ROWH];   // 48 KB single f16 plane
    float  sred[2][KSPLIT][16][16];         // 16 KB
};
#define DYN_SMEM_BYTES ((int)sizeof(SMem))

__global__ __launch_bounds__(THREADS, 2) void setconv_mma_kernel(
    const float* __restrict__ x, const float* __restrict__ y,
    const float* __restrict__ t, const float* __restrict__ sigma,
    const float* __restrict__ W, const float* __restrict__ bias,
    float* __restrict__ out)
{
    extern __shared__ __align__(16) unsigned char dynsm[];
    SMem& u = *reinterpret_cast<SMem*>(dynsm);
    __shared__ float sWt[CCH][OCH];
    __shared__ float sb[OCH];
    __shared__ float yout[M_B][CCH + 1];

    const int tid  = threadIdx.x;
    const int warp = tid >> 5, lane = tid & 31;
    const int b  = blockIdx.x / MTILES;
    const int mt = blockIdx.x % MTILES;
    const int mbase = mt * M_B;
    const int mg = warp >> 3;      // m-group 0..1 (16 m each)
    const int ks = warp & 7;       // k-split 0..7 (128 n each)

    const float sg0 = sigma[0];
    bool uniform = true;
    #pragma unroll
    for (int c = 1; c < CCH; c++) uniform &= (sigma[c] == sg0);
    // q0 = -0.5*log2(e)/s^2; scl = sqrt(-q0) so exp2(q0*d^2) = exp2(-(scl*d)^2)
    const float q0  = -0.72134752044448170f * ex2f(-2.0f * sg0 * 1.4426950408889634f);
    const float scl = sqrtf(-q0);

    // ---- stage x (scaled), y (f16), W, bias ----
    {
        const float xs = uniform ? scl : 1.0f;
        for (int i = tid; i < NOBS; i += THREADS)
            u.sx[i] = xs * x[b * NOBS + i];
    }
    {
        const float4* yb = (const float4*)(y + (size_t)b * NOBS * CCH);
        #pragma unroll
        for (int r = 0; r < NOBS * CCH / 4 / THREADS; r++) {   // 8 rounds
            int j = tid + THREADS * r;
            int n = j >> 2, c4 = j & 3;
            float4 v = yb[j];
            uint2 pk;
            pk.x = packh2(v.x, v.y);
            pk.y = packh2(v.z, v.w);
            *(uint2*)&u.syh[n][c4 * 4] = pk;
        }
    }
    for (int i = tid; i < OCH * CCH; i += THREADS) {
        int o = i / CCH, c = i % CCH;
        sWt[c][o] = W[i];
    }
    if (tid < OCH) sb[tid] = bias[tid];

    __syncthreads();

    if (uniform) {
        const int g  = lane >> 2;        // 0..7
        const int tq = lane & 3;         // 0..3
        const float t0 = scl * t[b * MOUT + mbase + mg * 16 + g];
        const float t1 = scl * t[b * MOUT + mbase + mg * 16 + g + 8];

        float c00 = 0.f, c01 = 0.f, c02 = 0.f, c03 = 0.f;   // channels 0-7
        float c10 = 0.f, c11 = 0.f, c12 = 0.f, c13 = 0.f;   // channels 8-15

        const int kbase = ks * KPW;
        const float* sxw = &u.sx[kbase + 2 * tq];
        const uint32_t lmw = s2u(&u.syh[kbase + (lane & 15)][0])
                           + ((lane & 16) ? 16u : 0u);

        // prologue: prefetch ktile 0
        float2 xa = *(const float2*)&sxw[0];
        float2 xb = *(const float2*)&sxw[8];
        uint32_t bh[4];
        ldm_x4_t(bh[0], bh[1], bh[2], bh[3], lmw);

        #pragma unroll
        for (int kt = 0; kt < KTILES; kt++) {
            float2 nxa, nxb;
            uint32_t nbh[4];
            if (kt + 1 < KTILES) {
                nxa = *(const float2*)&sxw[(kt + 1) * 16];
                nxb = *(const float2*)&sxw[(kt + 1) * 16 + 8];
                ldm_x4_t(nbh[0], nbh[1], nbh[2], nbh[3],
                         lmw + (uint32_t)(kt + 1) * (16 * ROWB));
            }

            float d;
            d = xa.x - t0; const float w00 = ex2f(-d * d);
            d = xa.y - t0; const float w01 = ex2f(-d * d);
            d = xa.x - t1; const float w10 = ex2f(-d * d);
            d = xa.y - t1; const float w11 = ex2f(-d * d);
            d = xb.x - t0; const float w02 = ex2f(-d * d);
            d = xb.y - t0; const float w03 = ex2f(-d * d);
            d = xb.x - t1; const float w12 = ex2f(-d * d);
            d = xb.y - t1; const float w13 = ex2f(-d * d);

            const uint32_t a0 = packh2(w00, w01);
            const uint32_t a1 = packh2(w10, w11);
            const uint32_t a2 = packh2(w02, w03);
            const uint32_t a3 = packh2(w12, w13);

            mma16816(c00, c01, c02, c03, a0, a1, a2, a3, bh[0], bh[1]);
            mma16816(c10, c11, c12, c13, a0, a1, a2, a3, bh[2], bh[3]);

            xa = nxa; xb = nxb;
            #pragma unroll
            for (int j = 0; j < 4; j++) bh[j] = nbh[j];
        }

        // sred is a distinct region: no barrier needed before writing
        const int col0 = 2 * tq;
        *(float2*)&u.sred[mg][ks][g][col0]          = make_float2(c00, c01);
        *(float2*)&u.sred[mg][ks][g + 8][col0]      = make_float2(c02, c03);
        *(float2*)&u.sred[mg][ks][g][8 + col0]      = make_float2(c10, c11);
        *(float2*)&u.sred[mg][ks][g + 8][8 + col0]  = make_float2(c12, c13);
    } else {
        // ---- general per-channel-sigma fallback (slow, correct) ----
        float q[CCH];
        #pragma unroll
        for (int c = 0; c < CCH; c++)
            q[c] = -0.72134752044448170f * ex2f(-2.0f * sigma[c] * 1.4426950408889634f);
        const int ml = lane & 15;
        const int half = lane >> 4;
        const float tm = t[b * MOUT + mbase + mg * 16 + ml];
        float acc[CCH];
        #pragma unroll
        for (int c = 0; c < CCH; c++) acc[c] = 0.0f;
        for (int nn = ks * KPW + half; nn < (ks + 1) * KPW; nn += 2) {
            const float xv = u.sx[nn];
            const float dd = (xv - tm) * (xv - tm);
            const __half2* row = (const __half2*)&u.syh[nn][0];
            #pragma unroll
            for (int c2 = 0; c2 < 8; c2++) {
                const float2 yh = __half22float2(row[c2]);
                acc[2 * c2]     += ex2f(q[2 * c2] * dd) * yh.x;
                acc[2 * c2 + 1] += ex2f(q[2 * c2 + 1] * dd) * yh.y;
            }
        }
        #pragma unroll
        for (int c = 0; c < CCH; c++)
            acc[c] += __shfl_xor_sync(0xffffffffu, acc[c], 16);
        if (half == 0)
            #pragma unroll
            for (int c = 0; c < CCH; c++) u.sred[mg][ks][ml][c] = acc[c];
    }

    __syncthreads();

    // ---- reduce 8 k-splits -> yout (512 sums, 1 per thread) ----
    {
        const int mgi = tid >> 8;
        const int m   = (tid >> 4) & 15;
        const int c   = tid & 15;
        float s = 0.0f;
        #pragma unroll
        for (int k = 0; k < KSPLIT; k++) s += u.sred[mgi][k][m][c];
        yout[mgi * 16 + m][c] = s;
    }
    __syncthreads();

    // ---- 16->32 linear + store (1024 outputs, 2 per thread) ----
    const int m_l = tid >> 4;           // 0..31
    const int ob  = (tid & 15) * 2;     // 0..30
    float yv[CCH];
    #pragma unroll
    for (int c = 0; c < CCH; c++) yv[c] = yout[m_l][c];
    float res[2];
    #pragma unroll
    for (int j = 0; j < 2; j++) {
        const int o = ob + j;
        float a = sb[o];
        #pragma unroll
        for (int c = 0; c < CCH; c++) a += yv[c] * sWt[c][o];
        res[j] = a;
    }
    *(float2*)(out + (((size_t)b * MOUT + mbase + m_l) * OCH) + ob) =
        make_float2(res[0], res[1]);
}

extern "C" void kernel_launch(void* const* d_in, const int* in_sizes, int n_in,
                              void* d_out, int out_size)
{
    const float* x     = (const float*)d_in[0];
    const float* y     = (const float*)d_in[1];
    const float* t     = (const float*)d_in[2];
    const float* sigma = (const float*)d_in[3];
    const float* W     = (const float*)d_in[4];
    const float* bias  = (const float*)d_in[5];
    float* out = (float*)d_out;

    cudaFuncSetAttribute(setconv_mma_kernel,
                         cudaFuncAttributeMaxDynamicSharedMemorySize, DYN_SMEM_BYTES);
    setconv_mma_kernel<<<BATCH * MTILES, THREADS, DYN_SMEM_BYTES>>>(
        x, y, t, sigma, W, bias, out);
}

// round 8
// speedup vs baseline: 2.1420x; 1.0870x over previous
#include <cuda_runtime.h>
#include <cuda_fp16.h>
#include <cstdint>
#include <math.h>

#define BATCH 8
#define NOBS 1024
#define MOUT 1024
#define CCH 16
#define OCH 32
#define THREADS 512
#define M_B 32
#define MTILES (MOUT / M_B)     // 32 -> grid 256
#define KSPLIT 16
#define KPW (NOBS / KSPLIT)     // 64 per warp
#define KTILES (KPW / 16)       // 4 k-tiles
#define ROWH 24                 // halves per y row: 16 data + 8 pad = 48B
#define ROWB (ROWH * 2)         // 48 bytes

__device__ __forceinline__ float ex2f(float v) {
    float r; asm("ex2.approx.ftz.f32 %0, %1;" : "=f"(r) : "f"(v)); return r;
}
__device__ __forceinline__ uint32_t s2u(const void* p) {
    return (uint32_t)__cvta_generic_to_shared(p);
}
__device__ __forceinline__ uint32_t packh2(float lo, float hi) {
    uint32_t r; asm("cvt.rn.f16x2.f32 %0, %1, %2;" : "=r"(r) : "f"(hi), "f"(lo)); return r;
}
__device__ __forceinline__ void ldm_x4_t(uint32_t& r0, uint32_t& r1, uint32_t& r2,
                                         uint32_t& r3, uint32_t addr) {
    asm volatile("ldmatrix.sync.aligned.m8n8.x4.trans.shared.b16 {%0,%1,%2,%3}, [%4];"
                 : "=r"(r0), "=r"(r1), "=r"(r2), "=r"(r3) : "r"(addr));
}
__device__ __forceinline__ void mma16816(float& c0, float& c1, float& c2, float& c3,
                                         uint32_t a0, uint32_t a1, uint32_t a2, uint32_t a3,
                                         uint32_t b0, uint32_t b1) {
    asm volatile("mma.sync.aligned.m16n8k16.row.col.f32.f16.f16.f32 "
                 "{%0,%1,%2,%3}, {%4,%5,%6,%7}, {%8,%9}, {%0,%1,%2,%3};"
                 : "+f"(c0), "+f"(c1), "+f"(c2), "+f"(c3)
                 : "r"(a0), "r"(a1), "r"(a2), "r"(a3), "r"(b0), "r"(b1));
}

struct SMem {
    float  sx[NOBS];                        // 4 KB (scaled by s in uniform mode)
    __align__(16) __half syh[NOBS][ROWH];   // 48 KB single f16 plane
    float  sred[KSPLIT][M_B][CCH];          // 32 KB
};
#define DYN_SMEM_BYTES ((int)sizeof(SMem))

__global__ __launch_bounds__(THREADS, 2) void setconv_mma_kernel(
    const float* __restrict__ x, const float* __restrict__ y,
    const float* __restrict__ t, const float* __restrict__ sigma,
    const float* __restrict__ W, const float* __restrict__ bias,
    float* __restrict__ out)
{
    extern __shared__ __align__(16) unsigned char dynsm[];
    SMem& u = *reinterpret_cast<SMem*>(dynsm);
    __shared__ float sWt[CCH][OCH];
    __shared__ float sb[OCH];
    __shared__ float yout[M_B][CCH + 1];

    const int tid  = threadIdx.x;
    const int warp = tid >> 5, lane = tid & 31;
    const int b  = blockIdx.x / MTILES;
    const int mt = blockIdx.x % MTILES;
    const int mbase = mt * M_B;
    const int ks = warp;            // k-split 0..15 (64 n each), warp owns all 32 m

    const float sg0 = sigma[0];
    bool uniform = true;
    #pragma unroll
    for (int c = 1; c < CCH; c++) uniform &= (sigma[c] == sg0);
    // q0 = -0.5*log2(e)/s^2; scl = sqrt(-q0) so exp2(q0*d^2) = exp2(-(scl*d)^2)
    const float q0  = -0.72134752044448170f * ex2f(-2.0f * sg0 * 1.4426950408889634f);
    const float scl = sqrtf(-q0);

    // ---- stage x (scaled), y (f16), W, bias ----
    {
        const float xs = uniform ? scl : 1.0f;
        for (int i = tid; i < NOBS; i += THREADS)
            u.sx[i] = xs * x[b * NOBS + i];
    }
    {
        const float4* yb = (const float4*)(y + (size_t)b * NOBS * CCH);
        #pragma unroll
        for (int r = 0; r < NOBS * CCH / 4 / THREADS; r++) {   // 8 rounds
            int j = tid + THREADS * r;
            int n = j >> 2, c4 = j & 3;
            float4 v = yb[j];
            uint2 pk;
            pk.x = packh2(v.x, v.y);
            pk.y = packh2(v.z, v.w);
            *(uint2*)&u.syh[n][c4 * 4] = pk;
        }
    }
    for (int i = tid; i < OCH * CCH; i += THREADS) {
        int o = i / CCH, c = i % CCH;
        sWt[c][o] = W[i];
    }
    if (tid < OCH) sb[tid] = bias[tid];

    __syncthreads();

    if (uniform) {
        const int g  = lane >> 2;        // 0..7
        const int tq = lane & 3;         // 0..3
        // m-fragment 0: rows g, g+8 ; fragment 1: rows 16+g, 24+g
        const float t0 = scl * t[b * MOUT + mbase + g];
        const float t1 = scl * t[b * MOUT + mbase + g + 8];
        const float t2 = scl * t[b * MOUT + mbase + 16 + g];
        const float t3 = scl * t[b * MOUT + mbase + 24 + g];

        float c00 = 0.f, c01 = 0.f, c02 = 0.f, c03 = 0.f;   // frag0 ch0-7
        float c10 = 0.f, c11 = 0.f, c12 = 0.f, c13 = 0.f;   // frag0 ch8-15
        float c20 = 0.f, c21 = 0.f, c22 = 0.f, c23 = 0.f;   // frag1 ch0-7
        float c30 = 0.f, c31 = 0.f, c32 = 0.f, c33 = 0.f;   // frag1 ch8-15

        const int kbase = ks * KPW;
        const float* sxw = &u.sx[kbase + 2 * tq];
        const uint32_t lmw = s2u(&u.syh[kbase + (lane & 15)][0])
                           + ((lane & 16) ? 16u : 0u);

        // prologue: prefetch ktile 0
        float2 xa = *(const float2*)&sxw[0];
        float2 xb = *(const float2*)&sxw[8];
        uint32_t bh[4];
        ldm_x4_t(bh[0], bh[1], bh[2], bh[3], lmw);

        #pragma unroll
        for (int kt = 0; kt < KTILES; kt++) {
            float2 nxa, nxb;
            uint32_t nbh[4];
            if (kt + 1 < KTILES) {
                nxa = *(const float2*)&sxw[(kt + 1) * 16];
                nxb = *(const float2*)&sxw[(kt + 1) * 16 + 8];
                ldm_x4_t(nbh[0], nbh[1], nbh[2], nbh[3],
                         lmw + (uint32_t)(kt + 1) * (16 * ROWB));
            }

            float d;
            // fragment 0 (t0, t1)
            d = xa.x - t0; const float w00 = ex2f(-d * d);
            d = xa.y - t0; const float w01 = ex2f(-d * d);
            d = xa.x - t1; const float w10 = ex2f(-d * d);
            d = xa.y - t1; const float w11 = ex2f(-d * d);
            d = xb.x - t0; const float w02 = ex2f(-d * d);
            d = xb.y - t0; const float w03 = ex2f(-d * d);
            d = xb.x - t1; const float w12 = ex2f(-d * d);
            d = xb.y - t1; const float w13 = ex2f(-d * d);
            const uint32_t a0 = packh2(w00, w01);
            const uint32_t a1 = packh2(w10, w11);
            const uint32_t a2 = packh2(w02, w03);
            const uint32_t a3 = packh2(w12, w13);
            mma16816(c00, c01, c02, c03, a0, a1, a2, a3, bh[0], bh[1]);
            mma16816(c10, c11, c12, c13, a0, a1, a2, a3, bh[2], bh[3]);

            // fragment 1 (t2, t3) — same x, same B
            d = xa.x - t2; const float v00 = ex2f(-d * d);
            d = xa.y - t2; const float v01 = ex2f(-d * d);
            d = xa.x - t3; const float v10 = ex2f(-d * d);
            d = xa.y - t3; const float v11 = ex2f(-d * d);
            d = xb.x - t2; const float v02 = ex2f(-d * d);
            d = xb.y - t2; const float v03 = ex2f(-d * d);
            d = xb.x - t3; const float v12 = ex2f(-d * d);
            d = xb.y - t3; const float v13 = ex2f(-d * d);
            const uint32_t e0 = packh2(v00, v01);
            const uint32_t e1 = packh2(v10, v11);
            const uint32_t e2 = packh2(v02, v03);
            const uint32_t e3 = packh2(v12, v13);
            mma16816(c20, c21, c22, c23, e0, e1, e2, e3, bh[0], bh[1]);
            mma16816(c30, c31, c32, c33, e0, e1, e2, e3, bh[2], bh[3]);

            xa = nxa; xb = nxb;
            #pragma unroll
            for (int j = 0; j < 4; j++) bh[j] = nbh[j];
        }

        // sred distinct region: no barrier needed before writing
        const int col0 = 2 * tq;
        *(float2*)&u.sred[ks][g][col0]           = make_float2(c00, c01);
        *(float2*)&u.sred[ks][g + 8][col0]       = make_float2(c02, c03);
        *(float2*)&u.sred[ks][g][8 + col0]       = make_float2(c10, c11);
        *(float2*)&u.sred[ks][g + 8][8 + col0]   = make_float2(c12, c13);
        *(float2*)&u.sred[ks][16 + g][col0]      = make_float2(c20, c21);
        *(float2*)&u.sred[ks][24 + g][col0]      = make_float2(c22, c23);
        *(float2*)&u.sred[ks][16 + g][8 + col0]  = make_float2(c30, c31);
        *(float2*)&u.sred[ks][24 + g][8 + col0]  = make_float2(c32, c33);
    } else {
        // ---- general per-channel-sigma fallback (slow, correct) ----
        float q[CCH];
        #pragma unroll
        for (int c = 0; c < CCH; c++)
            q[c] = -0.72134752044448170f * ex2f(-2.0f * sigma[c] * 1.4426950408889634f);
        const float tm = t[b * MOUT + mbase + lane];   // lane = m (0..31)
        float acc[CCH];
        #pragma unroll
        for (int c = 0; c < CCH; c++) acc[c] = 0.0f;
        for (int nn = ks * KPW; nn < (ks + 1) * KPW; nn++) {
            const float xv = u.sx[nn];
            const float dd = (xv - tm) * (xv - tm);
            const __half2* row = (const __half2*)&u.syh[nn][0];
            #pragma unroll
            for (int c2 = 0; c2 < 8; c2++) {
                const float2 yh = __half22float2(row[c2]);
                acc[2 * c2]     += ex2f(q[2 * c2] * dd) * yh.x;
                acc[2 * c2 + 1] += ex2f(q[2 * c2 + 1] * dd) * yh.y;
            }
        }
        #pragma unroll
        for (int c = 0; c < CCH; c++) u.sred[ks][lane][c] = acc[c];
    }

    __syncthreads();

    // ---- reduce 16 k-splits -> yout (512 sums, 1 per thread) ----
    {
        const int m = tid >> 4;        // 0..31
        const int c = tid & 15;
        float s = 0.0f;
        #pragma unroll
        for (int k = 0; k < KSPLIT; k++) s += u.sred[k][m][c];
        yout[m][c] = s;
    }
    __syncthreads();

    // ---- 16->32 linear: thread = (o, m-pair); W loaded once, yout broadcast ----
    const int o  = tid & 31;            // 0..31, distinct per lane
    const int mp = tid >> 5;            // 0..15 (constant within warp)
    float wv[CCH];
    #pragma unroll
    for (int c = 0; c < CCH; c++) wv[c] = sWt[c][o];
    const float bv = sb[o];
    #pragma unroll
    for (int j = 0; j < 2; j++) {
        const int m = 2 * mp + j;
        float a = bv;
        #pragma unroll
        for (int c = 0; c < CCH; c++) a += yout[m][c] * wv[c];
        out[((size_t)b * MOUT + mbase + m) * OCH + o] = a;
    }
}

extern "C" void kernel_launch(void* const* d_in, const int* in_sizes, int n_in,
                              void* d_out, int out_size)
{
    const float* x     = (const float*)d_in[0];
    const float* y     = (const float*)d_in[1];
    const float* t     = (const float*)d_in[2];
    const float* sigma = (const float*)d_in[3];
    const float* W     = (const float*)d_in[4];
    const float* bias  = (const float*)d_in[5];
    float* out = (float*)d_out;

    cudaFuncSetAttribute(setconv_mma_kernel,
                         cudaFuncAttributeMaxDynamicSharedMemorySize, DYN_SMEM_BYTES);
    setconv_mma_kernel<<<BATCH * MTILES, THREADS, DYN_SMEM_BYTES>>>(
        x, y, t, sigma, W, bias, out);
}

// round 9
// speedup vs baseline: 2.2669x; 1.0583x over previous
#include <cuda_runtime.h>
#include <cuda_fp16.h>
#include <cstdint>
#include <math.h>

#define BATCH 8
#define NOBS 1024
#define MOUT 1024
#define CCH 16
#define OCH 32
#define THREADS 512
#define M_B 32                  // m per tile
#define M_SUPER 64              // m per block (2 tiles)
#define MSTILES (MOUT / M_SUPER) // 16 -> grid 128
#define KSPLIT 16
#define KPW (NOBS / KSPLIT)     // 64 per warp
#define KTILES (KPW / 16)       // 4 k-tiles
#define ROWH 24                 // halves per y row: 16 data + 8 pad = 48B
#define ROWB (ROWH * 2)         // 48 bytes

__device__ __forceinline__ float ex2f(float v) {
    float r; asm("ex2.approx.ftz.f32 %0, %1;" : "=f"(r) : "f"(v)); return r;
}
__device__ __forceinline__ uint32_t s2u(const void* p) {
    return (uint32_t)__cvta_generic_to_shared(p);
}
__device__ __forceinline__ uint32_t packh2(float lo, float hi) {
    uint32_t r; asm("cvt.rn.f16x2.f32 %0, %1, %2;" : "=r"(r) : "f"(hi), "f"(lo)); return r;
}
__device__ __forceinline__ void ldm_x4_t(uint32_t& r0, uint32_t& r1, uint32_t& r2,
                                         uint32_t& r3, uint32_t addr) {
    asm volatile("ldmatrix.sync.aligned.m8n8.x4.trans.shared.b16 {%0,%1,%2,%3}, [%4];"
                 : "=r"(r0), "=r"(r1), "=r"(r2), "=r"(r3) : "r"(addr));
}
__device__ __forceinline__ void mma16816(float& c0, float& c1, float& c2, float& c3,
                                         uint32_t a0, uint32_t a1, uint32_t a2, uint32_t a3,
                                         uint32_t b0, uint32_t b1) {
    asm volatile("mma.sync.aligned.m16n8k16.row.col.f32.f16.f16.f32 "
                 "{%0,%1,%2,%3}, {%4,%5,%6,%7}, {%8,%9}, {%0,%1,%2,%3};"
                 : "+f"(c0), "+f"(c1), "+f"(c2), "+f"(c3)
                 : "r"(a0), "r"(a1), "r"(a2), "r"(a3), "r"(b0), "r"(b1));
}

struct SMem {
    float  sx[NOBS];                        // 4 KB (scaled by s in uniform mode)
    __align__(16) __half syh[NOBS][ROWH];   // 48 KB single f16 plane
    float  sred[KSPLIT][M_B][CCH];          // 32 KB
};
#define DYN_SMEM_BYTES ((int)sizeof(SMem))

__global__ __launch_bounds__(THREADS, 2) void setconv_mma_kernel(
    const float* __restrict__ x, const float* __restrict__ y,
    const float* __restrict__ t, const float* __restrict__ sigma,
    const float* __restrict__ W, const float* __restrict__ bias,
    float* __restrict__ out)
{
    extern __shared__ __align__(16) unsigned char dynsm[];
    SMem& u = *reinterpret_cast<SMem*>(dynsm);
    __shared__ float sWt[CCH][OCH];
    __shared__ float sb[OCH];
    __shared__ float yout[M_B][CCH + 1];

    const int tid  = threadIdx.x;
    const int warp = tid >> 5, lane = tid & 31;
    const int b   = blockIdx.x / MSTILES;
    const int mst = blockIdx.x % MSTILES;
    const int msbase = mst * M_SUPER;
    const int ks = warp;            // k-split 0..15 (64 n each), warp owns all 32 m

    const float sg0 = sigma[0];
    bool uniform = true;
    #pragma unroll
    for (int c = 1; c < CCH; c++) uniform &= (sigma[c] == sg0);
    // q0 = -0.5*log2(e)/s^2; scl = sqrt(-q0) so exp2(q0*d^2) = exp2(-(scl*d)^2)
    const float q0  = -0.72134752044448170f * ex2f(-2.0f * sg0 * 1.4426950408889634f);
    const float scl = sqrtf(-q0);

    // ---- stage x (scaled), y (f16), W, bias — ONCE per block ----
    {
        const float xs = uniform ? scl : 1.0f;
        for (int i = tid; i < NOBS; i += THREADS)
            u.sx[i] = xs * x[b * NOBS + i];
    }
    {
        const float4* yb = (const float4*)(y + (size_t)b * NOBS * CCH);
        #pragma unroll
        for (int r = 0; r < NOBS * CCH / 4 / THREADS; r++) {   // 8 rounds
            int j = tid + THREADS * r;
            int n = j >> 2, c4 = j & 3;
            float4 v = yb[j];
            uint2 pk;
            pk.x = packh2(v.x, v.y);
            pk.y = packh2(v.z, v.w);
            *(uint2*)&u.syh[n][c4 * 4] = pk;
        }
    }
    for (int i = tid; i < OCH * CCH; i += THREADS) {
        int o = i / CCH, c = i % CCH;
        sWt[c][o] = W[i];
    }
    if (tid < OCH) sb[tid] = bias[tid];

    __syncthreads();

    // per-warp mainloop constants (tile-independent)
    const int g  = lane >> 2;        // 0..7
    const int tq = lane & 3;         // 0..3
    const int kbase = ks * KPW;
    const float* sxw = &u.sx[kbase + 2 * tq];
    const uint32_t lmw = s2u(&u.syh[kbase + (lane & 15)][0])
                       + ((lane & 16) ? 16u : 0u);

    #pragma unroll 1
    for (int half = 0; half < 2; half++) {
        const int mbase = msbase + half * M_B;

        if (uniform) {
            // m-fragment 0: rows g, g+8 ; fragment 1: rows 16+g, 24+g
            const float t0 = scl * t[b * MOUT + mbase + g];
            const float t1 = scl * t[b * MOUT + mbase + g + 8];
            const float t2 = scl * t[b * MOUT + mbase + 16 + g];
            const float t3 = scl * t[b * MOUT + mbase + 24 + g];

            float c00 = 0.f, c01 = 0.f, c02 = 0.f, c03 = 0.f;
            float c10 = 0.f, c11 = 0.f, c12 = 0.f, c13 = 0.f;
            float c20 = 0.f, c21 = 0.f, c22 = 0.f, c23 = 0.f;
            float c30 = 0.f, c31 = 0.f, c32 = 0.f, c33 = 0.f;

            // prologue: prefetch ktile 0
            float2 xa = *(const float2*)&sxw[0];
            float2 xb = *(const float2*)&sxw[8];
            uint32_t bh[4];
            ldm_x4_t(bh[0], bh[1], bh[2], bh[3], lmw);

            #pragma unroll
            for (int kt = 0; kt < KTILES; kt++) {
                float2 nxa, nxb;
                uint32_t nbh[4];
                if (kt + 1 < KTILES) {
                    nxa = *(const float2*)&sxw[(kt + 1) * 16];
                    nxb = *(const float2*)&sxw[(kt + 1) * 16 + 8];
                    ldm_x4_t(nbh[0], nbh[1], nbh[2], nbh[3],
                             lmw + (uint32_t)(kt + 1) * (16 * ROWB));
                }

                float d;
                d = xa.x - t0; const float w00 = ex2f(-d * d);
                d = xa.y - t0; const float w01 = ex2f(-d * d);
                d = xa.x - t1; const float w10 = ex2f(-d * d);
                d = xa.y - t1; const float w11 = ex2f(-d * d);
                d = xb.x - t0; const float w02 = ex2f(-d * d);
                d = xb.y - t0; const float w03 = ex2f(-d * d);
                d = xb.x - t1; const float w12 = ex2f(-d * d);
                d = xb.y - t1; const float w13 = ex2f(-d * d);
                const uint32_t a0 = packh2(w00, w01);
                const uint32_t a1 = packh2(w10, w11);
                const uint32_t a2 = packh2(w02, w03);
                const uint32_t a3 = packh2(w12, w13);
                mma16816(c00, c01, c02, c03, a0, a1, a2, a3, bh[0], bh[1]);
                mma16816(c10, c11, c12, c13, a0, a1, a2, a3, bh[2], bh[3]);

                d = xa.x - t2; const float v00 = ex2f(-d * d);
                d = xa.y - t2; const float v01 = ex2f(-d * d);
                d = xa.x - t3; const float v10 = ex2f(-d * d);
                d = xa.y - t3; const float v11 = ex2f(-d * d);
                d = xb.x - t2; const float v02 = ex2f(-d * d);
                d = xb.y - t2; const float v03 = ex2f(-d * d);
                d = xb.x - t3; const float v12 = ex2f(-d * d);
                d = xb.y - t3; const float v13 = ex2f(-d * d);
                const uint32_t e0 = packh2(v00, v01);
                const uint32_t e1 = packh2(v10, v11);
                const uint32_t e2 = packh2(v02, v03);
                const uint32_t e3 = packh2(v12, v13);
                mma16816(c20, c21, c22, c23, e0, e1, e2, e3, bh[0], bh[1]);
                mma16816(c30, c31, c32, c33, e0, e1, e2, e3, bh[2], bh[3]);

                xa = nxa; xb = nxb;
                #pragma unroll
                for (int j = 0; j < 4; j++) bh[j] = nbh[j];
            }

            // sred distinct region: tile0 reduce reads are barrier-separated
            const int col0 = 2 * tq;
            *(float2*)&u.sred[ks][g][col0]           = make_float2(c00, c01);
            *(float2*)&u.sred[ks][g + 8][col0]       = make_float2(c02, c03);
            *(float2*)&u.sred[ks][g][8 + col0]       = make_float2(c10, c11);
            *(float2*)&u.sred[ks][g + 8][8 + col0]   = make_float2(c12, c13);
            *(float2*)&u.sred[ks][16 + g][col0]      = make_float2(c20, c21);
            *(float2*)&u.sred[ks][24 + g][col0]      = make_float2(c22, c23);
            *(float2*)&u.sred[ks][16 + g][8 + col0]  = make_float2(c30, c31);
            *(float2*)&u.sred[ks][24 + g][8 + col0]  = make_float2(c32, c33);
        } else {
            // ---- general per-channel-sigma fallback (slow, correct) ----
            float q[CCH];
            #pragma unroll
            for (int c = 0; c < CCH; c++)
                q[c] = -0.72134752044448170f * ex2f(-2.0f * sigma[c] * 1.4426950408889634f);
            const float tm = t[b * MOUT + mbase + lane];   // lane = m (0..31)
            float acc[CCH];
            #pragma unroll
            for (int c = 0; c < CCH; c++) acc[c] = 0.0f;
            for (int nn = ks * KPW; nn < (ks + 1) * KPW; nn++) {
                const float xv = u.sx[nn];
                const float dd = (xv - tm) * (xv - tm);
                const __half2* row = (const __half2*)&u.syh[nn][0];
                #pragma unroll
                for (int c2 = 0; c2 < 8; c2++) {
                    const float2 yh = __half22float2(row[c2]);
                    acc[2 * c2]     += ex2f(q[2 * c2] * dd) * yh.x;
                    acc[2 * c2 + 1] += ex2f(q[2 * c2 + 1] * dd) * yh.y;
                }
            }
            #pragma unroll
            for (int c = 0; c < CCH; c++) u.sred[ks][lane][c] = acc[c];
        }

        __syncthreads();   // sred complete; also fences prior tile's yout readers

        // ---- reduce 16 k-splits -> yout (512 sums, 1 per thread) ----
        {
            const int m = tid >> 4;        // 0..31
            const int c = tid & 15;
            float s = 0.0f;
            #pragma unroll
            for (int k = 0; k < KSPLIT; k++) s += u.sred[k][m][c];
            yout[m][c] = s;
        }
        __syncthreads();   // yout ready; all sred reads done (next tile may rewrite)

        // ---- 16->32 linear: thread = (o, m-pair); W once, yout broadcast ----
        const int o  = tid & 31;
        const int mp = tid >> 5;
        float wv[CCH];
        #pragma unroll
        for (int c = 0; c < CCH; c++) wv[c] = sWt[c][o];
        const float bv = sb[o];
        #pragma unroll
        for (int j = 0; j < 2; j++) {
            const int m = 2 * mp + j;
            float a = bv;
            #pragma unroll
            for (int c = 0; c < CCH; c++) a += yout[m][c] * wv[c];
            out[((size_t)b * MOUT + mbase + m) * OCH + o] = a;
        }
    }
}

extern "C" void kernel_launch(void* const* d_in, const int* in_sizes, int n_in,
                              void* d_out, int out_size)
{
    const float* x     = (const float*)d_in[0];
    const float* y     = (const float*)d_in[1];
    const float* t     = (const float*)d_in[2];
    const float* sigma = (const float*)d_in[3];
    const float* W     = (const float*)d_in[4];
    const float* bias  = (const float*)d_in[5];
    float* out = (float*)d_out;

    cudaFuncSetAttribute(setconv_mma_kernel,
                         cudaFuncAttributeMaxDynamicSharedMemorySize, DYN_SMEM_BYTES);
    setconv_mma_kernel<<<BATCH * MSTILES, THREADS, DYN_SMEM_BYTES>>>(
        x, y, t, sigma, W, bias, out);
}